// round 1
// baseline (speedup 1.0000x reference)
#include <cuda_runtime.h>
#include <cuda_bf16.h>
#include <cstdint>

// Histogram_15126874816754:
//   out[b, (p>0), y, x] += (|p| - MEAN)/STD   over 8M events, then clip at 1.0.
// Inputs (metadata order): x:int32[N], y:int32[N], p:f32[N], b:int32[N],
//                          width:int32[1], height:int32[1], batch_size:int32[1]
// Output: f32[B*2*H*W]

#define MEAN_C 0.0f
#define STD_C  20.0f
#define CLIP_MAX_C 1.0f

// ---------------------------------------------------------------------------
// Scatter pass: 4 events per thread via 128-bit loads; RED.E.ADD.F32 atomics
// into the (L2-resident, 59 MB) output image.
// ---------------------------------------------------------------------------
__global__ void __launch_bounds__(256)
hist_scatter_kernel(const int* __restrict__ xs,
                    const int* __restrict__ ys,
                    const float* __restrict__ ps,
                    const int* __restrict__ bs,
                    const int* __restrict__ wp,
                    const int* __restrict__ hp,
                    float* __restrict__ out,
                    int n)
{
    const int W = __ldg(wp);
    const int H = __ldg(hp);

    const int n4   = n >> 2;          // full vector groups
    const int rem  = n & 3;

    int i = blockIdx.x * blockDim.x + threadIdx.x;

    if (i < n4) {
        const int4   xv = __ldg(reinterpret_cast<const int4*>(xs) + i);
        const int4   yv = __ldg(reinterpret_cast<const int4*>(ys) + i);
        const float4 pv = __ldg(reinterpret_cast<const float4*>(ps) + i);
        const int4   bv = __ldg(reinterpret_cast<const int4*>(bs) + i);

        // lane 0
        {
            int pos = pv.x > 0.0f;
            long long idx = (((long long)(bv.x * 2 + pos) * H + yv.x) * W + xv.x);
            atomicAdd(out + idx, (fabsf(pv.x) - MEAN_C) * (1.0f / STD_C));
        }
        // lane 1
        {
            int pos = pv.y > 0.0f;
            long long idx = (((long long)(bv.y * 2 + pos) * H + yv.y) * W + xv.y);
            atomicAdd(out + idx, (fabsf(pv.y) - MEAN_C) * (1.0f / STD_C));
        }
        // lane 2
        {
            int pos = pv.z > 0.0f;
            long long idx = (((long long)(bv.z * 2 + pos) * H + yv.z) * W + xv.z);
            atomicAdd(out + idx, (fabsf(pv.z) - MEAN_C) * (1.0f / STD_C));
        }
        // lane 3
        {
            int pos = pv.w > 0.0f;
            long long idx = (((long long)(bv.w * 2 + pos) * H + yv.w) * W + xv.w);
            atomicAdd(out + idx, (fabsf(pv.w) - MEAN_C) * (1.0f / STD_C));
        }
    } else if (i == n4 && rem) {
        // scalar tail (unused for N=8M but keeps the kernel shape-generic)
        for (int k = n4 * 4; k < n; ++k) {
            int   xk = xs[k], yk = ys[k], bk = bs[k];
            float pk = ps[k];
            int   pos = pk > 0.0f;
            long long idx = (((long long)(bk * 2 + pos) * H + yk) * W + xk);
            atomicAdd(out + idx, (fabsf(pk) - MEAN_C) * (1.0f / STD_C));
        }
    }
}

// ---------------------------------------------------------------------------
// Clip pass: out = min(out, 1.0), vectorized float4.
// ---------------------------------------------------------------------------
__global__ void __launch_bounds__(256)
hist_clip_kernel(float* __restrict__ out, int n)
{
    const int n4 = n >> 2;
    int i = blockIdx.x * blockDim.x + threadIdx.x;

    if (i < n4) {
        float4* o4 = reinterpret_cast<float4*>(out);
        float4 v = o4[i];
        v.x = fminf(v.x, CLIP_MAX_C);
        v.y = fminf(v.y, CLIP_MAX_C);
        v.z = fminf(v.z, CLIP_MAX_C);
        v.w = fminf(v.w, CLIP_MAX_C);
        o4[i] = v;
    } else if (i == n4) {
        for (int k = n4 * 4; k < n; ++k)
            out[k] = fminf(out[k], CLIP_MAX_C);
    }
}

// ---------------------------------------------------------------------------
extern "C" void kernel_launch(void* const* d_in, const int* in_sizes, int n_in,
                              void* d_out, int out_size)
{
    const int*   xs = (const int*)  d_in[0];
    const int*   ys = (const int*)  d_in[1];
    const float* ps = (const float*)d_in[2];
    const int*   bs = (const int*)  d_in[3];
    const int*   wp = (const int*)  d_in[4];
    const int*   hp = (const int*)  d_in[5];
    // d_in[6] = batch_size (implied by out_size; unused on device)

    float* out = (float*)d_out;
    const int n = in_sizes[0];

    // 1) zero the accumulation image (DMA fill, graph-capturable)
    cudaMemsetAsync(d_out, 0, (size_t)out_size * sizeof(float), 0);

    // 2) scatter-add
    {
        const int n4 = n >> 2;
        const int rem = n & 3;
        const int total_threads = n4 + (rem ? 1 : 0);
        const int blocks = (total_threads + 255) / 256;
        hist_scatter_kernel<<<blocks, 256>>>(xs, ys, ps, bs, wp, hp, out, n);
    }

    // 3) clip
    {
        const int n4 = out_size >> 2;
        const int rem = out_size & 3;
        const int total_threads = n4 + (rem ? 1 : 0);
        const int blocks = (total_threads + 255) / 256;
        hist_clip_kernel<<<blocks, 256>>>(out, out_size);
    }
}